// round 2
// baseline (speedup 1.0000x reference)
#include <cuda_runtime.h>
#include <math.h>

#define N_NODES 50000
#define N_EDGES 600000
#define F 128
#define NGRAPH 1024

// ---------------- scratch (device globals; no allocation allowed) ----------------
__device__ float d_bufA[N_NODES * F];
__device__ float d_bufB[N_NODES * F];
__device__ int   d_deg[N_NODES];
__device__ float d_dinv[N_NODES];
__device__ int   d_rowptr[N_NODES + 1];
__device__ int   d_fill[N_NODES];
__device__ int   d_col[N_EDGES];
__device__ int   d_bsum[1024];
__device__ int   d_gcnt[NGRAPH];
__device__ int   d_gptr[NGRAPH + 1];
__device__ float d_pool[NGRAPH * 2 * F];

// ---------------- setup kernels ----------------
__global__ void k_init() {
    int i = blockIdx.x * blockDim.x + threadIdx.x;
    int stride = gridDim.x * blockDim.x;
    for (int j = i; j < N_NODES; j += stride) d_deg[j] = 0;
    for (int j = i; j < NGRAPH; j += stride) d_gcnt[j] = 0;
}

__global__ void k_hist_edges(const int* __restrict__ ei) {
    int e = blockIdx.x * blockDim.x + threadIdx.x;
    if (e < N_EDGES) atomicAdd(&d_deg[ei[N_EDGES + e]], 1);
}

__global__ void k_hist_batch(const int* __restrict__ bi) {
    int v = blockIdx.x * blockDim.x + threadIdx.x;
    if (v < N_NODES) atomicAdd(&d_gcnt[bi[v]], 1);
}

__global__ void k_dinv() {
    int v = blockIdx.x * blockDim.x + threadIdx.x;
    if (v < N_NODES) d_dinv[v] = rsqrtf((float)d_deg[v] + 1.0f);
}

// exclusive scan: per-block partials
__global__ void k_scan_partial(const int* __restrict__ in, int* __restrict__ out,
                               int* __restrict__ bsums, int n) {
    __shared__ int s[1024];
    int t = threadIdx.x;
    int i = blockIdx.x * 1024 + t;
    int v = (i < n) ? in[i] : 0;
    s[t] = v;
    __syncthreads();
    for (int off = 1; off < 1024; off <<= 1) {
        int u = (t >= off) ? s[t - off] : 0;
        __syncthreads();
        s[t] += u;
        __syncthreads();
    }
    if (i < n) out[i] = s[t] - v;  // exclusive
    if (t == 1023) bsums[blockIdx.x] = s[1023];
}

__global__ void k_scan_top(int* __restrict__ b, int n, int* __restrict__ total) {
    __shared__ int s[1024];
    int t = threadIdx.x;
    int v = (t < n) ? b[t] : 0;
    s[t] = v;
    __syncthreads();
    for (int off = 1; off < 1024; off <<= 1) {
        int u = (t >= off) ? s[t - off] : 0;
        __syncthreads();
        s[t] += u;
        __syncthreads();
    }
    if (t < n) b[t] = s[t] - v;
    if (t == 1023) total[0] = s[1023];
}

__global__ void k_scan_add(int* __restrict__ out, const int* __restrict__ bsums, int n) {
    int i = blockIdx.x * 1024 + threadIdx.x;
    if (i < n) out[i] += bsums[blockIdx.x];
}

__global__ void k_copy_fill() {
    int i = blockIdx.x * blockDim.x + threadIdx.x;
    int stride = gridDim.x * blockDim.x;
    for (int j = i; j < N_NODES; j += stride) d_fill[j] = d_rowptr[j];
}

__global__ void k_fill(const int* __restrict__ ei) {
    int e = blockIdx.x * blockDim.x + threadIdx.x;
    if (e < N_EDGES) {
        int dst = ei[N_EDGES + e];
        int p = atomicAdd(&d_fill[dst], 1);
        d_col[p] = ei[e];
    }
}

// ---------------- GEMM: O[v,:] = dinv[v] * (X[v,:] @ W) ----------------
// block = 256 threads, tile 64 rows x 128 cols; thread = 4 rows x 8 cols.
__device__ __forceinline__ void fma4(float4& a, float s, const float4& v) {
    a.x = fmaf(s, v.x, a.x);
    a.y = fmaf(s, v.y, a.y);
    a.z = fmaf(s, v.z, a.z);
    a.w = fmaf(s, v.w, a.w);
}

__global__ __launch_bounds__(256) void k_gemm(const float* __restrict__ X,
                                              const float* __restrict__ W,
                                              float* __restrict__ O) {
    __shared__ float4 Ws[32][32];   // [k in chunk][col4]
    __shared__ float  xs[32][64];   // [k in chunk][row in tile]
    int tid = threadIdx.x;
    int cg = tid & 15;
    int rg = tid >> 4;
    int row0 = blockIdx.x * 64;

    float4 acc[4][2];
#pragma unroll
    for (int i = 0; i < 4; i++) {
        acc[i][0] = make_float4(0.f, 0.f, 0.f, 0.f);
        acc[i][1] = make_float4(0.f, 0.f, 0.f, 0.f);
    }

    const float4* X4 = (const float4*)X;
    const float4* W4 = (const float4*)W;

    for (int kk = 0; kk < 128; kk += 32) {
        // stage W chunk: 32x128 floats = 1024 float4
#pragma unroll
        for (int j = 0; j < 4; j++) {
            int idx = tid + j * 256;
            Ws[idx >> 5][idx & 31] = W4[(size_t)(kk + (idx >> 5)) * 32 + (idx & 31)];
        }
        // stage X chunk transposed: 64 rows x 32 k
#pragma unroll
        for (int j = 0; j < 2; j++) {
            int idx = tid + j * 256;
            int r = idx >> 3;
            int k4 = idx & 7;
            float4 v = make_float4(0.f, 0.f, 0.f, 0.f);
            if (row0 + r < N_NODES) v = X4[(size_t)(row0 + r) * 32 + (kk >> 2) + k4];
            xs[k4 * 4 + 0][r] = v.x;
            xs[k4 * 4 + 1][r] = v.y;
            xs[k4 * 4 + 2][r] = v.z;
            xs[k4 * 4 + 3][r] = v.w;
        }
        __syncthreads();
#pragma unroll
        for (int k = 0; k < 32; k++) {
            float4 xr = *(const float4*)&xs[k][rg * 4];
            float4 wa = Ws[k][cg];
            float4 wb = Ws[k][cg + 16];
            fma4(acc[0][0], xr.x, wa); fma4(acc[0][1], xr.x, wb);
            fma4(acc[1][0], xr.y, wa); fma4(acc[1][1], xr.y, wb);
            fma4(acc[2][0], xr.z, wa); fma4(acc[2][1], xr.z, wb);
            fma4(acc[3][0], xr.w, wa); fma4(acc[3][1], xr.w, wb);
        }
        __syncthreads();
    }

    float4* O4 = (float4*)O;
#pragma unroll
    for (int i = 0; i < 4; i++) {
        int r = row0 + rg * 4 + i;
        if (r < N_NODES) {
            float s = d_dinv[r];
            float4 a = acc[i][0];
            a.x *= s; a.y *= s; a.z *= s; a.w *= s;
            float4 b = acc[i][1];
            b.x *= s; b.y *= s; b.z *= s; b.w *= s;
            O4[(size_t)r * 32 + cg] = a;
            O4[(size_t)r * 32 + cg + 16] = b;
        }
    }
}

// ---------------- aggregation: out[v] = relu(dinv[v]*(g[v] + sum g[src]) + b) ----------------
__global__ __launch_bounds__(256) void k_agg(const float* __restrict__ Gf,
                                             const float* __restrict__ b,
                                             float* __restrict__ O) {
    int gw = (blockIdx.x * blockDim.x + threadIdx.x) >> 5;
    int lane = threadIdx.x & 31;
    if (gw >= N_NODES) return;
    const float4* G4 = (const float4*)Gf;
    float4 acc = G4[(size_t)gw * 32 + lane];  // self loop
    int beg = d_rowptr[gw], end = d_rowptr[gw + 1];
    for (int e = beg; e < end; e++) {
        int s = d_col[e];
        float4 v = G4[(size_t)s * 32 + lane];
        acc.x += v.x; acc.y += v.y; acc.z += v.z; acc.w += v.w;
    }
    float dv = d_dinv[gw];
    float4 bb = ((const float4*)b)[lane];
    float4 r;
    r.x = fmaxf(fmaf(dv, acc.x, bb.x), 0.f);
    r.y = fmaxf(fmaf(dv, acc.y, bb.y), 0.f);
    r.z = fmaxf(fmaf(dv, acc.z, bb.z), 0.f);
    r.w = fmaxf(fmaf(dv, acc.w, bb.w), 0.f);
    ((float4*)O)[(size_t)gw * 32 + lane] = r;
}

// ---------------- pooling: per-graph warp, max + mean ----------------
__global__ __launch_bounds__(256) void k_pool(const float* __restrict__ H) {
    int gw = (blockIdx.x * blockDim.x + threadIdx.x) >> 5;
    int lane = threadIdx.x & 31;
    if (gw >= NGRAPH) return;
    int beg = d_gptr[gw], end = d_gptr[gw + 1];
    const float4* H4 = (const float4*)H;
    float4 mx = make_float4(0.f, 0.f, 0.f, 0.f);
    float4 sm = make_float4(0.f, 0.f, 0.f, 0.f);
    for (int v = beg; v < end; v++) {
        float4 x = H4[(size_t)v * 32 + lane];
        mx.x = fmaxf(mx.x, x.x); mx.y = fmaxf(mx.y, x.y);
        mx.z = fmaxf(mx.z, x.z); mx.w = fmaxf(mx.w, x.w);
        sm.x += x.x; sm.y += x.y; sm.z += x.z; sm.w += x.w;
    }
    int cnt = end - beg;
    float inv = 1.f / (float)(cnt > 0 ? cnt : 1);
    float4* P4 = (float4*)d_pool;
    P4[gw * 64 + lane] = mx;
    float4 mn = make_float4(sm.x * inv, sm.y * inv, sm.z * inv, sm.w * inv);
    P4[gw * 64 + 32 + lane] = mn;
}

// ---------------- MLP head: one block per graph ----------------
__global__ __launch_bounds__(128) void k_mlp(const float* __restrict__ Wl1, const float* __restrict__ bl1,
                                             const float* __restrict__ Wl2, const float* __restrict__ bl2,
                                             const float* __restrict__ Wl3, const float* __restrict__ bl3,
                                             float* __restrict__ out) {
    __shared__ float gv[256];
    __shared__ float o1[128];
    __shared__ float red[128];
    int g = blockIdx.x;
    int t = threadIdx.x;
    gv[t] = d_pool[g * 256 + t];
    gv[t + 128] = d_pool[g * 256 + 128 + t];
    __syncthreads();
    float a = bl1[t];
#pragma unroll 8
    for (int k = 0; k < 256; k++) a = fmaf(gv[k], Wl1[k * 128 + t], a);
    o1[t] = fmaxf(a, 0.f);
    __syncthreads();
    float c = bl2[t];
#pragma unroll 8
    for (int k = 0; k < 128; k++) c = fmaf(o1[k], Wl2[k * 128 + t], c);
    c = fmaxf(c, 0.f);
    red[t] = c * Wl3[t];
    __syncthreads();
    for (int off = 64; off > 0; off >>= 1) {
        if (t < off) red[t] += red[t + off];
        __syncthreads();
    }
    if (t == 0) out[g] = 1.f / (1.f + expf(-(red[0] + bl3[0])));
}

// ---------------- launch ----------------
extern "C" void kernel_launch(void* const* d_in, const int* in_sizes, int n_in,
                              void* d_out, int out_size) {
    const float* x   = (const float*)d_in[0];
    const int*   ei  = (const int*)d_in[1];
    const int*   bi  = (const int*)d_in[2];
    const float* W0  = (const float*)d_in[3];
    const float* b0  = (const float*)d_in[4];
    const float* W1  = (const float*)d_in[5];
    const float* b1  = (const float*)d_in[6];
    const float* W2  = (const float*)d_in[7];
    const float* b2  = (const float*)d_in[8];
    const float* Wl1 = (const float*)d_in[9];
    const float* bl1 = (const float*)d_in[10];
    const float* Wl2 = (const float*)d_in[11];
    const float* bl2 = (const float*)d_in[12];
    const float* Wl3 = (const float*)d_in[13];
    const float* bl3 = (const float*)d_in[14];
    float* out = (float*)d_out;

    void* p;
    cudaGetSymbolAddress(&p, d_deg);    int* deg = (int*)p;
    cudaGetSymbolAddress(&p, d_rowptr); int* rowptr = (int*)p;
    cudaGetSymbolAddress(&p, d_bsum);   int* bsum = (int*)p;
    cudaGetSymbolAddress(&p, d_gcnt);   int* gcnt = (int*)p;
    cudaGetSymbolAddress(&p, d_gptr);   int* gptr = (int*)p;
    cudaGetSymbolAddress(&p, d_bufA);   float* bufA = (float*)p;
    cudaGetSymbolAddress(&p, d_bufB);   float* bufB = (float*)p;

    // ---- graph structure (once per call) ----
    k_init<<<64, 256>>>();
    k_hist_edges<<<(N_EDGES + 255) / 256, 256>>>(ei);
    k_hist_batch<<<(N_NODES + 255) / 256, 256>>>(bi);
    k_dinv<<<(N_NODES + 255) / 256, 256>>>();

    const int NB = (N_NODES + 1023) / 1024;  // 49
    k_scan_partial<<<NB, 1024>>>(deg, rowptr, bsum, N_NODES);
    k_scan_top<<<1, 1024>>>(bsum, NB, rowptr + N_NODES);
    k_scan_add<<<NB, 1024>>>(rowptr, bsum, N_NODES);
    k_copy_fill<<<64, 256>>>();
    k_fill<<<(N_EDGES + 255) / 256, 256>>>(ei);

    k_scan_partial<<<1, 1024>>>(gcnt, gptr, bsum, NGRAPH);
    k_scan_top<<<1, 1024>>>(bsum, 1, gptr + NGRAPH);
    k_scan_add<<<1, 1024>>>(gptr, bsum, NGRAPH);

    // ---- 3 GCN layers ----
    const int gemmGrid = (N_NODES + 63) / 64;
    const int aggGrid = (N_NODES * 32 + 255) / 256;
    k_gemm<<<gemmGrid, 256>>>(x, W0, bufB);
    k_agg<<<aggGrid, 256>>>(bufB, b0, bufA);
    k_gemm<<<gemmGrid, 256>>>(bufA, W1, bufB);
    k_agg<<<aggGrid, 256>>>(bufB, b1, bufA);
    k_gemm<<<gemmGrid, 256>>>(bufA, W2, bufB);
    k_agg<<<aggGrid, 256>>>(bufB, b2, bufA);

    // ---- pooling + head ----
    k_pool<<<(NGRAPH * 32 + 255) / 256, 256>>>(bufA);
    k_mlp<<<NGRAPH, 128>>>(Wl1, bl1, Wl2, bl2, Wl3, bl3, out);
}